// round 16
// baseline (speedup 1.0000x reference)
#include <cuda_runtime.h>

// MetaSR collapsed to a sub-pixel 3x3 conv (see R2 analysis):
//   rel = (j&1)*0.5 exactly, r_rev = 0.5 exactly -> MLP input has 4 values
//   (one per 2x2 phase) -> pw collapses to 4 tables of (576,3).
// pred[b,(2y+dy)*128+2x+dx,o] = sum_{c,ky,kx} feat[b,c,y+ky-1,x+kx-1]
//                                  * pw[dy*2+dx][(c*9+ky*3+kx)*3+o]
//
// R16: weights REGISTER-RESIDENT. Warp = (b, y, x-half, o, dy); lane = channel
// pair (32 lanes = all 64 ch -> warp-local reduction). 18 u64 weight regs per
// lane loaded once, reused over 4 passes of 8 px. Inner loop has NO weight
// loads: 30 LDG.64 + 144 FFMA2 per pass. fma pipe becomes the wall.

#define NB 4
#define NQ 16384
#define NOUT 1728
#define PH 66   // padded H/W

// g_pwB[j][pat]: j = (c*9+tap)*3 + o, pat = dy*2 + dx.
// Weight u64 for (c,tap,o,dy) = floats [j*4 + dy*2 .. +1] = (dx0, dx1).
__device__ __align__(16) float g_pwB[NOUT * 4];                 // 27648 B
__device__ __align__(16) float g_featP[NB * PH * PH * 64];      // padded, ch-last

// ---------------------------------------------------------------------------
// f32x2 packed helpers (PTX-only path; ptxas won't auto-fuse)
// ---------------------------------------------------------------------------
__device__ __forceinline__ unsigned long long pk2(float a, float b) {
    unsigned long long r;
    asm("mov.b64 %0, {%1, %2};" : "=l"(r) : "f"(a), "f"(b));
    return r;
}
__device__ __forceinline__ void upk2(unsigned long long v, float& a, float& b) {
    asm("mov.b64 {%0, %1}, %2;" : "=f"(a), "=f"(b) : "l"(v));
}
__device__ __forceinline__ void ffma2(unsigned long long& d,
                                      unsigned long long a, unsigned long long b) {
    asm("fma.rn.f32x2 %0, %1, %2, %0;" : "+l"(d) : "l"(a), "l"(b));
}
__device__ __forceinline__ unsigned long long addx2(unsigned long long a,
                                                    unsigned long long b) {
    unsigned long long d;
    asm("add.rn.f32x2 %0, %1, %2;" : "=l"(d) : "l"(a), "l"(b));
    return d;
}

// ---------------------------------------------------------------------------
// Prep kernel: 291 blocks x 256 threads, role-split.
//   [0,256):   transpose (b,y): feat row -> g_featP interior, float4 both ways
//   [256,283): pw tables (27 blocks) -> g_pwB[j][pat]
//   [283,291): zero the padded halo
// ---------------------------------------------------------------------------
__global__ __launch_bounds__(256) void k_prep(const float* __restrict__ feat,
                                              const float* __restrict__ w1,
                                              const float* __restrict__ b1,
                                              const float* __restrict__ w2,
                                              const float* __restrict__ b2) {
    __shared__ __align__(16) float sm[64 * 68];
    int bi = blockIdx.x;
    int t = threadIdx.x;

    if (bi < 256) {
        // ---- transpose: block = (b, y). 64c x 64x tile.
        int b = bi >> 6;
        int y = bi & 63;
        int x4 = t & 15;
        int cb = t >> 4;
#pragma unroll
        for (int pass = 0; pass < 4; ++pass) {
            int c = pass * 16 + cb;
            float4 v = *reinterpret_cast<const float4*>(
                feat + ((b * 64 + c) * 64 + y) * 64 + x4 * 4);
            *reinterpret_cast<float4*>(sm + c * 68 + x4 * 4) = v;
        }
        __syncthreads();
        int c4 = t & 15;
        int xb = t >> 4;
#pragma unroll
        for (int pass = 0; pass < 4; ++pass) {
            int x = pass * 16 + xb;
            float4 v = make_float4(sm[(c4 * 4 + 0) * 68 + x],
                                   sm[(c4 * 4 + 1) * 68 + x],
                                   sm[(c4 * 4 + 2) * 68 + x],
                                   sm[(c4 * 4 + 3) * 68 + x]);
            *reinterpret_cast<float4*>(
                g_featP + ((b * PH + y + 1) * PH + x + 1) * 64 + c4 * 4) = v;
        }
    } else if (bi < 283) {
        // ---- pw tables
        float* hdd = sm;            // [4][256]
        float* part = sm + 1024;    // [4][4][64]
        {
            float a0 = w1[t];
            float a1 = w1[256 + t];
            float a2 = w1[512 + t];
            float bb = b1[t];
#pragma unroll
            for (int pat = 0; pat < 4; ++pat) {
                float ry = (pat >> 1) ? 0.5f : 0.0f;
                float rx = (pat & 1) ? 0.5f : 0.0f;
                float v = ry * a0 + rx * a1 + 0.5f * a2 + bb;
                hdd[pat * 256 + t] = v > 0.0f ? v : 0.0f;
            }
        }
        __syncthreads();
        int jt = t & 63;
        int hc = t >> 6;
        int j = (bi - 256) * 64 + jt;
        int hb = hc * 64;
        float a0 = 0.f, a1 = 0.f, a2 = 0.f, a3 = 0.f;
        const float* w2p = w2 + hb * NOUT + j;
#pragma unroll 8
        for (int hh = 0; hh < 64; ++hh) {
            float wv = w2p[hh * NOUT];
            a0 += hdd[0 * 256 + hb + hh] * wv;
            a1 += hdd[1 * 256 + hb + hh] * wv;
            a2 += hdd[2 * 256 + hb + hh] * wv;
            a3 += hdd[3 * 256 + hb + hh] * wv;
        }
        part[(hc * 4 + 0) * 64 + jt] = a0;
        part[(hc * 4 + 1) * 64 + jt] = a1;
        part[(hc * 4 + 2) * 64 + jt] = a2;
        part[(hc * 4 + 3) * 64 + jt] = a3;
        __syncthreads();
        if (hc == 0) {
            float bias = b2[j];
#pragma unroll
            for (int pat = 0; pat < 4; ++pat) {   // pat = dy*2 + dx
                float s = part[(0 * 4 + pat) * 64 + jt] + part[(1 * 4 + pat) * 64 + jt] +
                          part[(2 * 4 + pat) * 64 + jt] + part[(3 * 4 + pat) * 64 + jt] + bias;
                g_pwB[j * 4 + pat] = s;
            }
        }
    } else {
        // ---- halo zero
        int hb = bi - 283;
        int b = hb >> 1;
        int halfsel = hb & 1;
        for (int idx = t; idx < 130 * 64; idx += 256) {
            int p = halfsel * 130 + (idx >> 6);
            int c = idx & 63;
            int y, x;
            if (p < 66) { y = 0; x = p; }
            else if (p < 132) { y = 65; x = p - 66; }
            else if (p < 196) { x = 0; y = p - 131; }
            else { x = 65; y = p - 195; }
            g_featP[((b * PH + y) * PH + x) * 64 + c] = 0.0f;
        }
    }
}

// ---------------------------------------------------------------------------
// Main conv kernel: 768 blocks x 128 threads. Warp wg = blockIdx*4 + warp:
//   ody = wg % 6 -> (o, dy); rest = wg / 6 -> (b, y, x-half).
// Lane owns channels {2*lane, 2*lane+1}; weights (2ch x 9tap, dx-paired) live
// in 18 u64 registers for the whole kernel. 4 passes of 8 px along the
// half-row; per pass: 30 LDG.64 (contiguous 256B/warp), 144 FFMA2, then a
// warp-local reduce-scatter (all 64 channels are in-warp) and 16 STG.32.
// ---------------------------------------------------------------------------
__global__ __launch_bounds__(128, 4) void k_main(float* __restrict__ out) {
    int t = threadIdx.x;
    int lane = t & 31;
    int wg = blockIdx.x * 4 + (t >> 5);
    int ody = wg % 6;
    int rest = wg / 6;            // 0..511
    int o = ody >> 1;
    int dy = ody & 1;
    int half = rest & 1;
    int y = (rest >> 1) & 63;
    int b = rest >> 7;
    int c0 = lane * 2;

    // One-time weight load: w[c][tap] = (w_dx0, w_dx1) for (c0+c, tap, o, dy).
    unsigned long long w[2][9];
#pragma unroll
    for (int c = 0; c < 2; ++c)
#pragma unroll
        for (int tap = 0; tap < 9; ++tap)
            w[c][tap] = *reinterpret_cast<const unsigned long long*>(
                g_pwB + (((c0 + c) * 9 + tap) * 3 + o) * 4 + dy * 2);

    const float* fb = g_featP + ((b * PH + y) * PH) * 64 + c0;

#pragma unroll 1
    for (int p = 0; p < 4; ++p) {
        int x0 = half * 32 + p * 8;     // padded cols x0..x0+9 (halo included)

        unsigned long long acc[8];
#pragma unroll
        for (int i = 0; i < 8; ++i) acc[i] = 0ull;

#pragma unroll
        for (int ky = 0; ky < 3; ++ky) {
            const float* rp = fb + (ky * PH + x0) * 64;
            unsigned long long fv[2][10];
#pragma unroll
            for (int i = 0; i < 10; ++i) {
                float2 f2 = *reinterpret_cast<const float2*>(rp + i * 64);
                fv[0][i] = pk2(f2.x, f2.x);
                fv[1][i] = pk2(f2.y, f2.y);
            }
#pragma unroll
            for (int kx = 0; kx < 3; ++kx)
#pragma unroll
                for (int c = 0; c < 2; ++c) {
                    unsigned long long wv = w[c][ky * 3 + kx];
#pragma unroll
                    for (int px = 0; px < 8; ++px)
                        ffma2(acc[px], fv[c][kx + px], wv);
                }
        }

        // Reduce-scatter over lane bits {1,2,4}: 8 -> 4 -> 2 -> 1 u64.
        // Lane ends owning px = 4*b0 + 2*b1 + b2.
#pragma unroll
        for (int m = 1, n = 8; m < 8; m <<= 1, n >>= 1) {
            int hlf = n >> 1;
            bool hi = (lane & m) != 0;
#pragma unroll
            for (int i = 0; i < 8; ++i) {
                if (i >= hlf) break;
                unsigned long long send = hi ? acc[i] : acc[i + hlf];
                unsigned long long r = __shfl_xor_sync(0xffffffffu, send, m);
                unsigned long long keep = hi ? acc[i + hlf] : acc[i];
                acc[i] = addx2(keep, r);
            }
        }
        // Bit 3: split the (dx0, dx1) halves of the surviving u64.
        float lo, hiv;
        upk2(acc[0], lo, hiv);
        bool b3 = (lane & 8) != 0;
        float send = b3 ? lo : hiv;
        float r = __shfl_xor_sync(0xffffffffu, send, 8);
        float mine = (b3 ? hiv : lo) + r;
        // Bit 4: plain butterfly (lanes 16-31 mirror 0-15).
        mine += __shfl_xor_sync(0xffffffffu, mine, 16);

        if (lane < 16) {
            int px = 4 * (lane & 1) + 2 * ((lane >> 1) & 1) + ((lane >> 2) & 1);
            int dx = (lane >> 3) & 1;
            int hrq = (2 * y + dy) * 128 + 2 * (x0 + px) + dx;
            out[(b * NQ + hrq) * 3 + o] = mine;
        }
    }
}

// ---------------------------------------------------------------------------
// Inputs (metadata order): feat, coord, cell, w1, b1, w2, b2.
// coord/cell are fully determined grids (collapsed analytically).
// ---------------------------------------------------------------------------
extern "C" void kernel_launch(void* const* d_in, const int* in_sizes, int n_in,
                              void* d_out, int out_size) {
    const float* feat = (const float*)d_in[0];
    const float* w1   = (const float*)d_in[3];
    const float* b1   = (const float*)d_in[4];
    const float* w2   = (const float*)d_in[5];
    const float* b2   = (const float*)d_in[6];
    float* out = (float*)d_out;

    k_prep<<<291, 256>>>(feat, w1, b1, w2, b2);
    k_main<<<768, 128>>>(out);
}

// round 17
// speedup vs baseline: 1.0968x; 1.0968x over previous
#include <cuda_runtime.h>

// MetaSR collapsed to a sub-pixel 3x3 conv (see R2 analysis):
//   rel = (j&1)*0.5 exactly, r_rev = 0.5 exactly -> MLP input has 4 values
//   (one per 2x2 phase) -> pw collapses to 4 tables of (576,3).
// pred[b,(2y+dy)*128+2x+dx,o] = sum_{c,ky,kx} feat[b,c,y+ky-1,x+kx-1]
//                                  * pw[dy*2+dx][(c*9+ky*3+kx)*3+o]
//
// R17: k_main is the proven R7 kernel (10.5us, best of 6 variants tried).
// The round's change is the transpose: vectorized both ends (2 LDG.128 +
// 8 STS + 8 LDS + 2 STG.128 per 32 floats), conflict-free banking, 512
// blocks. Targets the ~5us prep portion, not the mainloop.

#define NB 4
#define NQ 16384
#define NOUT 1728
#define PH 66   // padded H/W

// pw layout: idx = ((cc*9 + tap)*16 + cg)*12 + pat*3 + o   (c = cg*4+cc)
__device__ __align__(16) float g_pw[576 * 12];                  // 27648 B
__device__ __align__(16) float g_featP[NB * PH * PH * 64];      // padded, ch-last

// ---------------------------------------------------------------------------
// f32x2 packed helpers (PTX-only path; ptxas won't auto-fuse)
// ---------------------------------------------------------------------------
__device__ __forceinline__ unsigned long long pk2(float a, float b) {
    unsigned long long r;
    asm("mov.b64 %0, {%1, %2};" : "=l"(r) : "f"(a), "f"(b));
    return r;
}
__device__ __forceinline__ void upk2(unsigned long long v, float& a, float& b) {
    asm("mov.b64 {%0, %1}, %2;" : "=f"(a), "=f"(b) : "l"(v));
}
__device__ __forceinline__ void ffma2(unsigned long long& d,
                                      unsigned long long a, unsigned long long b) {
    asm("fma.rn.f32x2 %0, %1, %2, %0;" : "+l"(d) : "l"(a), "l"(b));
}

// ---------------------------------------------------------------------------
// Prep kernel: 547 blocks x 256 threads, role-split.
//   [0,512):   transpose (b, y, c-half): feat -> g_featP interior, vectorized
//   [512,539): pw tables (27 blocks)
//   [539,547): zero the padded halo
// ---------------------------------------------------------------------------
__global__ __launch_bounds__(256) void k_prep(const float* __restrict__ feat,
                                              const float* __restrict__ w1,
                                              const float* __restrict__ b1,
                                              const float* __restrict__ w2,
                                              const float* __restrict__ b2) {
    __shared__ __align__(16) float sm[32 * 68];   // tile[32][68] (2176 floats)
    int bi = blockIdx.x;
    int t = threadIdx.x;

    if (bi < 512) {
        // ---- transpose: block = (b, y, c-half). 32c x 64x tile.
        int b = bi >> 7;
        int y = (bi >> 1) & 63;
        int c0 = (bi & 1) * 32;
        // Phase 1: coalesced float4 loads of 32 channel-rows at row y.
        //   lane: x4 = t&15 (float4 along x), ci = t>>4 (0..15), 2 passes.
        //   STS.128 at tile idx16 = 17*cl + x4: per-octet distinct bank-quads.
        {
            int x4 = t & 15;
            int ci = t >> 4;
#pragma unroll
            for (int pass = 0; pass < 2; ++pass) {
                int cl = pass * 16 + ci;
                float4 v = *reinterpret_cast<const float4*>(
                    feat + ((b * 64 + c0 + cl) * 64 + y) * 64 + x4 * 4);
                *reinterpret_cast<float4*>(sm + cl * 68 + x4 * 4) = v;
            }
        }
        __syncthreads();
        // Phase 2: gather c-quads, STG.128 to channel-last featP.
        //   lane: x = t&63, g = t>>6 (0..3); q = g*2+pass (c-quad 0..7).
        //   LDS bank = (4*(cl+i) + x) mod 32: distinct across lanes (x-major).
        {
            int x = t & 63;
            int g = t >> 6;
#pragma unroll
            for (int pass = 0; pass < 2; ++pass) {
                int q = g * 2 + pass;          // 0..7
                int cl = q * 4;
                float4 v = make_float4(sm[(cl + 0) * 68 + x],
                                       sm[(cl + 1) * 68 + x],
                                       sm[(cl + 2) * 68 + x],
                                       sm[(cl + 3) * 68 + x]);
                *reinterpret_cast<float4*>(
                    g_featP + ((b * PH + y + 1) * PH + x + 1) * 64 + c0 + cl) = v;
            }
        }
    } else if (bi < 539) {
        // ---- pw tables
        float* hdd = sm;            // [4][256] (1024 floats)
        float* part = sm + 1024;    // [4][4][64] (1024 floats)
        {
            float a0 = w1[t];
            float a1 = w1[256 + t];
            float a2 = w1[512 + t];
            float bb = b1[t];
#pragma unroll
            for (int pat = 0; pat < 4; ++pat) {
                float ry = (pat >> 1) ? 0.5f : 0.0f;
                float rx = (pat & 1) ? 0.5f : 0.0f;
                float v = ry * a0 + rx * a1 + 0.5f * a2 + bb;
                hdd[pat * 256 + t] = v > 0.0f ? v : 0.0f;
            }
        }
        __syncthreads();
        int jt = t & 63;
        int hc = t >> 6;
        int j = (bi - 512) * 64 + jt;
        int hb = hc * 64;
        float a0 = 0.f, a1 = 0.f, a2 = 0.f, a3 = 0.f;
        const float* w2p = w2 + hb * NOUT + j;
#pragma unroll 8
        for (int hh = 0; hh < 64; ++hh) {
            float wv = w2p[hh * NOUT];
            a0 += hdd[0 * 256 + hb + hh] * wv;
            a1 += hdd[1 * 256 + hb + hh] * wv;
            a2 += hdd[2 * 256 + hb + hh] * wv;
            a3 += hdd[3 * 256 + hb + hh] * wv;
        }
        part[(hc * 4 + 0) * 64 + jt] = a0;
        part[(hc * 4 + 1) * 64 + jt] = a1;
        part[(hc * 4 + 2) * 64 + jt] = a2;
        part[(hc * 4 + 3) * 64 + jt] = a3;
        __syncthreads();
        if (hc == 0) {
            float bias = b2[j];
            int k = j / 3;
            int o = j - k * 3;
            int c = k / 9;
            int tap = k - c * 9;
            int cgi = c >> 2;
            int cci = c & 3;
            int base = ((cci * 9 + tap) * 16 + cgi) * 12 + o;
#pragma unroll
            for (int pat = 0; pat < 4; ++pat) {
                float s = part[(0 * 4 + pat) * 64 + jt] + part[(1 * 4 + pat) * 64 + jt] +
                          part[(2 * 4 + pat) * 64 + jt] + part[(3 * 4 + pat) * 64 + jt] + bias;
                g_pw[base + pat * 3] = s;
            }
        }
    } else {
        // ---- halo zero
        int hb = bi - 539;
        int b = hb >> 1;
        int halfsel = hb & 1;
        for (int idx = t; idx < 130 * 64; idx += 256) {
            int p = halfsel * 130 + (idx >> 6);
            int c = idx & 63;
            int y, x;
            if (p < 66) { y = 0; x = p; }
            else if (p < 132) { y = 65; x = p - 66; }
            else if (p < 196) { x = 0; y = p - 131; }
            else { x = 65; y = p - 195; }
            g_featP[((b * PH + y) * PH + x) * 64 + c] = 0.0f;
        }
    }
}

// ---------------------------------------------------------------------------
// Main conv kernel: R7 version verbatim (proven fastest of 6 variants).
// 512 blocks x 128 threads, single wave at 4 blocks/SM. Warp = 2 quads;
// lane: cg = lane&15 (4-ch group), sub = lane>>4. Thread: 4 ch x 9 taps x
// 4 px x 12 out = 864 packed f32x2 FMAs. Reduce-scatter; direct STG.
// ---------------------------------------------------------------------------
__global__ __launch_bounds__(128, 4) void k_main(float* __restrict__ out) {
    __shared__ __align__(16) float pw_sm[576 * 12];
    int t = threadIdx.x;
    {
        const float4* g4 = reinterpret_cast<const float4*>(g_pw);
        float4* s4 = reinterpret_cast<float4*>(pw_sm);
#pragma unroll
        for (int i = 0; i < 14; ++i) {
            int idx = t + i * 128;
            if (idx < 1728) s4[idx] = g4[idx];
        }
    }
    __syncthreads();

    int lane = t & 31;
    int warp = t >> 5;
    int cg = lane & 15;
    int sub = lane >> 4;
    int quad = (blockIdx.x * 4 + warp) * 2 + sub;   // 0..4095
    int b = quad >> 10;
    int rem = quad & 1023;
    int y = rem >> 4;
    int x0 = (rem & 15) << 2;

    unsigned long long acc[4][6];
#pragma unroll
    for (int px = 0; px < 4; ++px)
#pragma unroll
        for (int p = 0; p < 6; ++p) acc[px][p] = 0ull;

    int cb4 = cg * 4;

#pragma unroll
    for (int ky = 0; ky < 3; ++ky) {
        const float* rp = g_featP + ((b * PH + y + ky) * PH + x0) * 64 + cb4;
        float fr[6][4];
#pragma unroll
        for (int i = 0; i < 6; ++i) {
            float4 v = *reinterpret_cast<const float4*>(rp + i * 64);
            fr[i][0] = v.x; fr[i][1] = v.y; fr[i][2] = v.z; fr[i][3] = v.w;
        }
#pragma unroll
        for (int kx = 0; kx < 3; ++kx) {
#pragma unroll
            for (int cc = 0; cc < 4; ++cc) {
                const ulonglong2* wp = reinterpret_cast<const ulonglong2*>(
                    pw_sm + ((cc * 9 + ky * 3 + kx) * 16 + cg) * 12);
                ulonglong2 wa = wp[0];
                ulonglong2 wb = wp[1];
                ulonglong2 wc = wp[2];
#pragma unroll
                for (int px = 0; px < 4; ++px) {
                    float fv = fr[kx + px][cc];
                    unsigned long long fv2 = pk2(fv, fv);
                    ffma2(acc[px][0], fv2, wa.x);
                    ffma2(acc[px][1], fv2, wa.y);
                    ffma2(acc[px][2], fv2, wb.x);
                    ffma2(acc[px][3], fv2, wb.y);
                    ffma2(acc[px][4], fv2, wc.x);
                    ffma2(acc[px][5], fv2, wc.y);
                }
            }
        }
    }

    // Unpack to 48 scalars: v[j], j = px*12 + pat*3 + o
    float v[48];
#pragma unroll
    for (int px = 0; px < 4; ++px)
#pragma unroll
        for (int p = 0; p < 6; ++p) {
            float a, bb;
            upk2(acc[px][p], a, bb);
            v[px * 12 + 2 * p] = a;
            v[px * 12 + 2 * p + 1] = bb;
        }

    // Reduce-scatter across the 16 cg lanes: lane ends owning 3 consecutive
    // j at base = 24*b0 + 12*b1 + 6*b2 + 3*b3 (bits of cg).
#pragma unroll
    for (int m = 1, n = 48; m < 16; m <<= 1, n >>= 1) {
        int half = n >> 1;
        bool hi = (cg & m) != 0;
#pragma unroll
        for (int i = 0; i < 48; ++i) {
            if (i >= half) break;
            float send = hi ? v[i] : v[i + half];
            float r = __shfl_xor_sync(0xffffffffu, send, m);
            v[i] = (hi ? v[i + half] : v[i]) + r;
        }
    }

    int base = 24 * (cg & 1) + 12 * ((cg >> 1) & 1) + 6 * ((cg >> 2) & 1) + 3 * ((cg >> 3) & 1);
    int px = base / 12;
    int r12 = base - px * 12;
    int dy = r12 / 6;
    int r6 = r12 - dy * 6;
    int dx = r6 / 3;

    int hrq = (2 * y + dy) * 128 + 2 * (x0 + px) + dx;
    float* op = out + (b * NQ + hrq) * 3;
    op[0] = v[0];
    op[1] = v[1];
    op[2] = v[2];
}

// ---------------------------------------------------------------------------
// Inputs (metadata order): feat, coord, cell, w1, b1, w2, b2.
// coord/cell are fully determined grids (collapsed analytically).
// ---------------------------------------------------------------------------
extern "C" void kernel_launch(void* const* d_in, const int* in_sizes, int n_in,
                              void* d_out, int out_size) {
    const float* feat = (const float*)d_in[0];
    const float* w1   = (const float*)d_in[3];
    const float* b1   = (const float*)d_in[4];
    const float* w2   = (const float*)d_in[5];
    const float* b2   = (const float*)d_in[6];
    float* out = (float*)d_out;

    k_prep<<<547, 256>>>(feat, w1, b1, w2, b2);
    k_main<<<512, 128>>>(out);
}